// round 11
// baseline (speedup 1.0000x reference)
#include <cuda_runtime.h>
#include <cuda_fp16.h>

// Problem constants (fixed by the reference)
#define Nn   10000      // nodes
#define Ee   80000      // edges (excl. self loops)
#define Gg   16         // B*DAYS graphs
#define HC   128        // H*C_OUT
#define NEG  0.2f
#define PR   8          // rows per proj group
#define NPROJ (Nn / PR)             // 1250 proj groups
#define LOG2E 1.44269504088896f

#define GRID  592       // 4 blocks per SM (148 SMs), co-resident by launch_bounds
#define TPB   512
#define NWRP  16        // warps per block
#define GRPS  4         // 128-thread proj groups per block
#define CHUNK 17        // nodes per block in scan (592*17 >= 10000)

// ---- device scratch (allocation-free rule: __device__ globals) ----
__device__ __align__(16) __half g_emb_h[Nn * HC];     // fp16 projected embedding [N,128]
__device__ __align__(16) float g_asrc[Nn * 4];        // src logits * log2e [N,H]
__device__ __align__(16) float g_adst[Nn * 4];        // dst logits * log2e [N,H]
__device__ __align__(16) int g_xT[Nn * Gg];           // transposed x: [N,16]
__device__ __align__(16) float2 g_comb[Nn * Gg * 4];  // per (n,g,h): {u_bits, asrc[u][h]}
__device__ int g_row_ptr[Nn + 1];
__device__ int g_cursor[Nn];                          // INVARIANT: all-zero at launch entry
__device__ int g_edge_src[Ee + 3];                    // +3 pad (stays 0) for 3-deep prefetch
__device__ int g_bsum[GRID];

// grid barrier: count self-resets; gen is monotonic across launches (replay-safe)
__device__ unsigned g_bcount = 0;
__device__ volatile unsigned g_bgen = 0;

__device__ __forceinline__ void grid_bar() {
    __syncthreads();
    if (threadIdx.x == 0) {
        __threadfence();
        unsigned my = g_bgen;
        unsigned t = atomicAdd(&g_bcount, 1);
        if (t == GRID - 1) {
            g_bcount = 0;
            __threadfence();
            g_bgen = my + 1;
        } else {
            while (g_bgen == my) { }
            __threadfence();
        }
    }
    __syncthreads();
}

__device__ __forceinline__ float fexp2(float x) {
    float y;
    asm("ex2.approx.f32 %0, %1;" : "=f"(y) : "f"(x));
    return y;
}

__global__ void __launch_bounds__(TPB, 4)
k_all(const float* __restrict__ emb, const float* __restrict__ W,
      const float* __restrict__ att_s, const float* __restrict__ att_d,
      const int* __restrict__ x, const int* __restrict__ adj,
      const float* __restrict__ bias, float* __restrict__ out) {
    int tid = threadIdx.x;
    int b = blockIdx.x;

    __shared__ float sws[256];            // fused W@att: [k][(srcdst<<2)|h]
    __shared__ float se[GRPS][PR][32];
    __shared__ int svals[CHUNK];
    __shared__ int soff;

    // ================= Phase A: histogram + projection + x-transpose =================
    for (int e = b * TPB + tid; e < Ee; e += GRID * TPB)
        atomicAdd(&g_cursor[adj[Ee + e]], 1);          // adj[1] = dst

    if (tid < 256) {
        int k = tid >> 3, j = tid & 7, h = j & 3;
        const float* av = (j < 4) ? att_s : att_d;
        float a = 0.f;
#pragma unroll
        for (int c2 = 0; c2 < 32; c2++)
            a = fmaf(W[k * 128 + h * 32 + c2], av[h * 32 + c2], a);
        sws[tid] = a;
    }
    __syncthreads();

    {
        int grp = tid >> 7;          // 0..3
        int c = tid & 127;           // channel 0..127
        int gb = b * GRPS + grp;     // 592*4 = 2368 >= 1250 -> single pass
        bool act = gb < NPROJ;
        int n0 = gb * PR;
        if (act) {
#pragma unroll
            for (int i = 0; i < 2; i++) {
                int idx = i * 128 + c;
                se[grp][idx >> 5][idx & 31] = emb[n0 * 32 + idx];
            }
            int gg = c >> 3, i = c & 7;
            g_xT[(n0 + i) * Gg + gg] = x[gg * Nn + n0 + i];
        }
        asm volatile("bar.sync %0, %1;" :: "r"(grp + 1), "r"(128));
        if (act) {
            float acc[PR];
#pragma unroll
            for (int r = 0; r < PR; r++) acc[r] = 0.f;
            // four passes of 8 W-column registers (fits the 32-reg cap)
#pragma unroll
            for (int pass = 0; pass < 4; pass++) {
                float wcol[8];
#pragma unroll
                for (int k = 0; k < 8; k++) wcol[k] = W[(pass * 8 + k) * 128 + c];
#pragma unroll
                for (int r = 0; r < PR; r++) {
#pragma unroll
                    for (int k = 0; k < 8; k++)
                        acc[r] = fmaf(se[grp][r][pass * 8 + k], wcol[k], acc[r]);
                }
            }
#pragma unroll
            for (int r = 0; r < PR; r++)
                g_emb_h[(n0 + r) * 128 + c] = __float2half(acc[r]);
            if (c < 64) {
                int r = c >> 3, j = c & 7, h = j & 3;
                float a = 0.f;
#pragma unroll
                for (int k = 0; k < 32; k++) a = fmaf(se[grp][r][k], sws[k * 8 + j], a);
                a *= LOG2E;
                if (j < 4) g_asrc[(n0 + r) * 4 + h] = a;
                else       g_adst[(n0 + r) * 4 + h] = a;
            }
        }
    }
    grid_bar();   // ---- barrier 1: histogram + asrc + xT complete ----

    // ================= Phase B: CSR scan (warp 0) + comb table (all threads) =================
    if (tid < 32) {
        int lane = tid;
        int n = b * CHUNK + lane;
        int c0 = (lane < CHUNK && n < Nn) ? g_cursor[n] : 0;
        int pre = c0;
#pragma unroll
        for (int o = 1; o < 32; o <<= 1) {
            int t = __shfl_up_sync(0xffffffffu, pre, o);
            if (lane >= o) pre += t;
        }
        if (lane < CHUNK) svals[lane] = pre - c0;
        if (lane == 31) g_bsum[b] = pre;   // block total
    }

    // comb: per (n,g): u = xT[n*16+g]; entries h=0..3: {u_bits, asrc[u][h]}
    for (int i = b * TPB + tid; i < Nn * Gg; i += GRID * TPB) {
        int u = g_xT[i];
        float4 a4 = *(const float4*)(g_asrc + u * 4);
        float uf = __int_as_float(u);
        float4* dst = (float4*)(g_comb + i * 4);
        dst[0] = make_float4(uf, a4.x, uf, a4.y);
        dst[1] = make_float4(uf, a4.z, uf, a4.w);
    }
    grid_bar();   // ---- barrier 2: block sums + comb visible ----

    if (tid < 32) {
        int lane = tid;
        int acc = 0;
        for (int i = lane; i < b; i += 32) acc += g_bsum[i];
#pragma unroll
        for (int o = 16; o; o >>= 1) acc += __shfl_down_sync(0xffffffffu, acc, o);
        if (lane == 0) soff = acc;
    }
    __syncthreads();
    {
        int off = soff;
        if (tid < CHUNK) {
            int n = b * CHUNK + tid;
            if (n < Nn) {
                int p = off + svals[tid];
                g_row_ptr[n] = p;
                g_cursor[n] = p;
            }
        }
        if (b == 0 && tid == 0) g_row_ptr[Nn] = Ee;
    }
    grid_bar();   // ---- barrier 3: row_ptr/cursor ready ----

    // ================= Phase C: CSR fill =================
    for (int e = b * TPB + tid; e < Ee; e += GRID * TPB) {
        int d = adj[Ee + e];
        int p = atomicAdd(&g_cursor[d], 1);
        g_edge_src[p] = adj[e];          // adj[0] = src
    }
    grid_bar();   // ---- barrier 4: edge_src ready ----

    // ================= Phase D: GAT (persistent warps, 1 graph per warp) =================
    for (int n = b * TPB + tid; n < Nn; n += GRID * TPB) g_cursor[n] = 0;  // restore invariant

    int lane = tid & 31;
    int h = lane >> 3;           // head (lane owns channels [4*lane, 4*lane+4))
    const __half* __restrict__ embp = g_emb_h;
    const float2* __restrict__ comb = g_comb;

    for (int w = b * NWRP + (tid >> 5); w < Nn * Gg; w += GRID * NWRP) {
        int v = w >> 4;              // 16 consecutive warps share v -> L1 hits
        int g = w & 15;
        int co = g * 4 + h;          // lane's comb entry within node's 64-entry row

        // self loop via comb
        float2 uav = comb[v * 64 + co];
        int vemb = __float_as_int(uav.x);
        float adst = g_adst[vemb * 4 + h];

        float acc[4];
        float s;
        {
            float a0 = uav.y + adst;
            a0 = fmaxf(a0, NEG * a0);
            float e0 = fexp2(a0);
            s = e0;
            uint2 q = *(const uint2*)(embp + vemb * 128 + lane * 4);
            float2 f0 = __half22float2(*(const __half2*)&q.x);
            float2 f1 = __half22float2(*(const __half2*)&q.y);
            acc[0] = e0 * f0.x; acc[1] = e0 * f0.y;
            acc[2] = e0 * f1.x; acc[3] = e0 * f1.y;
        }

        int idx = g_row_ptr[v];
        int end = g_row_ptr[v + 1];
        // 3-deep pipeline: edge_src +3, comb +2, msg +1 (pad slots read 0 -> valid node 0)
        int j0 = g_edge_src[idx];
        int j1 = g_edge_src[idx + 1];
        float2 c0 = comb[j0 * 64 + co];
        float2 c1 = comb[j1 * 64 + co];
        uint2 m0 = *(const uint2*)(embp + __float_as_int(c0.x) * 128 + lane * 4);
        int j2 = g_edge_src[idx + 2];
        for (; idx < end; idx++) {
            uint2 m1 = *(const uint2*)(embp + __float_as_int(c1.x) * 128 + lane * 4);
            float a = c0.y + adst;
            c0 = c1;
            c1 = comb[j2 * 64 + co];
            j2 = g_edge_src[idx + 3];

            a = fmaxf(a, NEG * a);
            float wi = fexp2(a);
            s += wi;
            float2 f0 = __half22float2(*(const __half2*)&m0.x);
            float2 f1 = __half22float2(*(const __half2*)&m0.y);
            acc[0] = fmaf(wi, f0.x, acc[0]);
            acc[1] = fmaf(wi, f0.y, acc[1]);
            acc[2] = fmaf(wi, f1.x, acc[2]);
            acc[3] = fmaf(wi, f1.y, acc[3]);
            m0 = m1;
        }

        float inv = __fdividef(1.f, s + 1e-16f);
        float4 bb = *(const float4*)(bias + lane * 4);
        float4 o;
        o.x = fmaf(acc[0], inv, bb.x);
        o.y = fmaf(acc[1], inv, bb.y);
        o.z = fmaf(acc[2], inv, bb.z);
        o.w = fmaf(acc[3], inv, bb.w);
        *(float4*)(out + ((size_t)g * Nn + v) * 128 + lane * 4) = o;
    }
}

extern "C" void kernel_launch(void* const* d_in, const int* in_sizes, int n_in,
                              void* d_out, int out_size) {
    const int*   x     = (const int*)d_in[0];     // [B,DAYS,N] = [16,10000]
    const int*   adj   = (const int*)d_in[1];     // [2,E]
    const float* emb   = (const float*)d_in[2];   // [N,32]
    const float* W     = (const float*)d_in[3];   // [32,128]
    const float* att_s = (const float*)d_in[4];   // [4,32]
    const float* att_d = (const float*)d_in[5];   // [4,32]
    const float* bias  = (const float*)d_in[6];   // [128]
    float* out = (float*)d_out;                   // [16,10000,128]

    k_all<<<GRID, TPB>>>(emb, W, att_s, att_d, x, adj, bias, out);
}

// round 12
// speedup vs baseline: 1.4311x; 1.4311x over previous
#include <cuda_runtime.h>
#include <cuda_fp16.h>

// Problem constants (fixed by the reference)
#define Nn   10000      // nodes
#define Ee   80000      // edges (excl. self loops)
#define Gg   16         // B*DAYS graphs
#define HC   128        // H*C_OUT
#define NEG  0.2f
#define PR   8          // rows per proj group
#define NPROJ (Nn / PR)             // 1250 proj groups
#define LOG2E 1.44269504088896f

#define GRID  296       // 2 blocks per SM (148 SMs), co-resident by launch_bounds
#define TPB   640
#define NWRP  20        // warps per block
#define GRPS  5         // 128-thread proj groups per block
#define CHUNK 34        // nodes per block in scan (296*34 >= 10000)

// ---- device scratch (allocation-free rule: __device__ globals) ----
__device__ __align__(16) __half g_emb_h[Nn * HC];     // fp16 projected embedding [N,128]
__device__ __align__(16) float g_asrc[Nn * 4];        // src logits * log2e [N,H]
__device__ __align__(16) float g_adst[Nn * 4];        // dst logits * log2e [N,H]
__device__ __align__(16) int g_xT[Nn * Gg];           // transposed x: [N,16]
__device__ __align__(16) float2 g_comb[Nn * Gg * 4];  // per (n,g,h): {u_bits, asrc[u][h]}
__device__ int g_row_ptr[Nn + 1];
__device__ int g_cursor[Nn];                          // INVARIANT: all-zero at launch entry
__device__ int g_edge_src[Ee + 4];                    // +4 pad (stays 0) for 4-deep prefetch
__device__ int g_bsum[GRID];

// grid barrier: count self-resets; gen is monotonic across launches (replay-safe)
__device__ unsigned g_bcount = 0;
__device__ volatile unsigned g_bgen = 0;

__device__ __forceinline__ void grid_bar() {
    __syncthreads();
    if (threadIdx.x == 0) {
        __threadfence();
        unsigned my = g_bgen;
        unsigned t = atomicAdd(&g_bcount, 1);
        if (t == GRID - 1) {
            g_bcount = 0;
            __threadfence();
            g_bgen = my + 1;
        } else {
            while (g_bgen == my) { }
            __threadfence();
        }
    }
    __syncthreads();
}

__device__ __forceinline__ float fexp2(float x) {
    float y;
    asm("ex2.approx.f32 %0, %1;" : "=f"(y) : "f"(x));
    return y;
}

__global__ void __launch_bounds__(TPB, 2)
k_all(const float* __restrict__ emb, const float* __restrict__ W,
      const float* __restrict__ att_s, const float* __restrict__ att_d,
      const int* __restrict__ x, const int* __restrict__ adj,
      const float* __restrict__ bias, float* __restrict__ out) {
    int tid = threadIdx.x;
    int b = blockIdx.x;

    __shared__ float sws[256];            // fused W@att: [k][(srcdst<<2)|h]
    __shared__ float se[GRPS][PR][32];
    __shared__ int svals[CHUNK];
    __shared__ int soff;

    // ================= Phase A: histogram + projection + x-transpose =================
    for (int e = b * TPB + tid; e < Ee; e += GRID * TPB)
        atomicAdd(&g_cursor[adj[Ee + e]], 1);          // adj[1] = dst

    if (tid < 256) {
        int k = tid >> 3, j = tid & 7, h = j & 3;
        const float* av = (j < 4) ? att_s : att_d;
        float a = 0.f;
#pragma unroll
        for (int c2 = 0; c2 < 32; c2++)
            a = fmaf(W[k * 128 + h * 32 + c2], av[h * 32 + c2], a);
        sws[tid] = a;
    }
    __syncthreads();

    {
        int grp = tid >> 7;          // 0..4
        int c = tid & 127;           // channel 0..127
        int gb = b * GRPS + grp;     // 296*5 = 1480 >= 1250 -> single pass
        bool act = gb < NPROJ;
        int n0 = gb * PR;
        if (act) {
#pragma unroll
            for (int i = 0; i < 2; i++) {
                int idx = i * 128 + c;
                se[grp][idx >> 5][idx & 31] = emb[n0 * 32 + idx];
            }
            int gg = c >> 3, i = c & 7;
            g_xT[(n0 + i) * Gg + gg] = x[gg * Nn + n0 + i];
        }
        asm volatile("bar.sync %0, %1;" :: "r"(grp + 1), "r"(128));
        if (act) {
            float acc[PR];
#pragma unroll
            for (int r = 0; r < PR; r++) acc[r] = 0.f;
            // two passes of 16 W-column registers
#pragma unroll
            for (int pass = 0; pass < 2; pass++) {
                float wcol[16];
#pragma unroll
                for (int k = 0; k < 16; k++) wcol[k] = W[(pass * 16 + k) * 128 + c];
#pragma unroll
                for (int r = 0; r < PR; r++) {
#pragma unroll
                    for (int k = 0; k < 16; k++)
                        acc[r] = fmaf(se[grp][r][pass * 16 + k], wcol[k], acc[r]);
                }
            }
#pragma unroll
            for (int r = 0; r < PR; r++)
                g_emb_h[(n0 + r) * 128 + c] = __float2half(acc[r]);
            if (c < 64) {
                int r = c >> 3, j = c & 7, h = j & 3;
                float a = 0.f;
#pragma unroll
                for (int k = 0; k < 32; k++) a = fmaf(se[grp][r][k], sws[k * 8 + j], a);
                a *= LOG2E;
                if (j < 4) g_asrc[(n0 + r) * 4 + h] = a;
                else       g_adst[(n0 + r) * 4 + h] = a;
            }
        }
    }
    grid_bar();   // ---- barrier 1: histogram + asrc + xT complete ----

    // ================= Phase B: CSR scan (warp 0) + comb table (all threads) =================
    if (tid < 32) {
        int lane = tid;
        int i0 = b * CHUNK + lane * 2;
        int c0 = (lane < 17 && i0 < Nn) ? g_cursor[i0] : 0;
        int c1 = (lane < 17 && i0 + 1 < Nn) ? g_cursor[i0 + 1] : 0;
        int lsum = c0 + c1;
        int pre = lsum;
#pragma unroll
        for (int o = 1; o < 32; o <<= 1) {
            int t = __shfl_up_sync(0xffffffffu, pre, o);
            if (lane >= o) pre += t;
        }
        int excl = pre - lsum;
        if (lane < 17) {
            svals[lane * 2] = excl;
            if (lane * 2 + 1 < CHUNK) svals[lane * 2 + 1] = excl + c0;
        }
        if (lane == 31) g_bsum[b] = pre;   // block total
    }

    // comb: per (n,g): u = xT[n*16+g]; entries h=0..3: {u_bits, asrc[u][h]}
    for (int i = b * TPB + tid; i < Nn * Gg; i += GRID * TPB) {
        int u = g_xT[i];
        float4 a4 = *(const float4*)(g_asrc + u * 4);
        float uf = __int_as_float(u);
        float4* dst = (float4*)(g_comb + i * 4);
        dst[0] = make_float4(uf, a4.x, uf, a4.y);
        dst[1] = make_float4(uf, a4.z, uf, a4.w);
    }
    grid_bar();   // ---- barrier 2: block sums + comb visible ----

    if (tid < 32) {
        int lane = tid;
        int acc = 0;
        for (int i = lane; i < b; i += 32) acc += g_bsum[i];
#pragma unroll
        for (int o = 16; o; o >>= 1) acc += __shfl_down_sync(0xffffffffu, acc, o);
        if (lane == 0) soff = acc;
    }
    __syncthreads();
    {
        int off = soff;
        if (tid < CHUNK) {
            int n = b * CHUNK + tid;
            if (n < Nn) {
                int p = off + svals[tid];
                g_row_ptr[n] = p;
                g_cursor[n] = p;
            }
        }
        if (b == 0 && tid == 0) g_row_ptr[Nn] = Ee;
    }
    grid_bar();   // ---- barrier 3: row_ptr/cursor ready ----

    // ================= Phase C: CSR fill =================
    for (int e = b * TPB + tid; e < Ee; e += GRID * TPB) {
        int d = adj[Ee + e];
        int p = atomicAdd(&g_cursor[d], 1);
        g_edge_src[p] = adj[e];          // adj[0] = src
    }
    grid_bar();   // ---- barrier 4: edge_src ready ----

    // ================= Phase D: GAT (persistent warps, 2 graphs per warp) =================
    for (int n = b * TPB + tid; n < Nn; n += GRID * TPB) g_cursor[n] = 0;  // restore invariant

    int lane = tid & 31;
    int gi = lane >> 4;          // graph within 2-chunk
    int sub = lane & 15;         // channel group: [8*sub, 8*sub+8)
    int h = sub >> 2;            // head
    const __half* __restrict__ embp = g_emb_h;
    const float2* __restrict__ comb = g_comb;

    for (int w = b * NWRP + (tid >> 5); w < Nn * 8; w += GRID * NWRP) {
        int v = w >> 3;              // consecutive warps share v -> L1 hits
        int gc = w & 7;              // 2-graph chunk
        int g = gc * 2 + gi;
        int co = g * 4 + h;          // lane's comb entry within node's 64-entry row

        // self loop via comb
        float2 uav = comb[v * 64 + co];
        int vemb = __float_as_int(uav.x);
        float adst = g_adst[vemb * 4 + h];

        float acc[8];
        float s;
        {
            float a0 = uav.y + adst;
            a0 = fmaxf(a0, NEG * a0);
            float e0 = fexp2(a0);
            s = e0;
            uint4 q = *(const uint4*)(embp + vemb * 128 + sub * 8);
            const __half2* hp = (const __half2*)&q;
#pragma unroll
            for (int k = 0; k < 4; k++) {
                float2 f = __half22float2(hp[k]);
                acc[2 * k] = e0 * f.x;
                acc[2 * k + 1] = e0 * f.y;
            }
        }

        int idx = g_row_ptr[v];
        int end = g_row_ptr[v + 1];
        // deep pipeline: edge_src +4, comb +3, msg +2 (pad slots read 0 -> valid node 0)
        int j0 = g_edge_src[idx];
        int j1 = g_edge_src[idx + 1];
        int j2 = g_edge_src[idx + 2];
        float2 c0 = comb[j0 * 64 + co];
        float2 c1 = comb[j1 * 64 + co];
        float2 c2 = comb[j2 * 64 + co];
        uint4 m0 = *(const uint4*)(embp + __float_as_int(c0.x) * 128 + sub * 8);
        uint4 m1 = *(const uint4*)(embp + __float_as_int(c1.x) * 128 + sub * 8);
        int j3 = g_edge_src[idx + 3];
        for (; idx < end; idx++) {
            // prefetch: msg for edge i+2 (addr from c2, loaded 2 iters ago),
            // comb for edge i+3 (index j3, loaded 1 iter ago), edge_src for i+4
            uint4 m2 = *(const uint4*)(embp + __float_as_int(c2.x) * 128 + sub * 8);
            float2 cn = comb[j3 * 64 + co];
            j3 = g_edge_src[idx + 4];

            float a = c0.y + adst;
            a = fmaxf(a, NEG * a);
            float wi = fexp2(a);
            s += wi;
            const __half2* hp = (const __half2*)&m0;
#pragma unroll
            for (int k = 0; k < 4; k++) {
                float2 f = __half22float2(hp[k]);
                acc[2 * k]     = fmaf(wi, f.x, acc[2 * k]);
                acc[2 * k + 1] = fmaf(wi, f.y, acc[2 * k + 1]);
            }
            c0 = c1; c1 = c2; c2 = cn;
            m0 = m1; m1 = m2;
        }

        float inv = __fdividef(1.f, s + 1e-16f);
        float* op = out + ((size_t)g * Nn + v) * 128 + sub * 8;
        const float* bp = bias + sub * 8;
#pragma unroll
        for (int k = 0; k < 2; k++) {
            float4 bb = *(const float4*)(bp + 4 * k);
            float4 o;
            o.x = fmaf(acc[4 * k], inv, bb.x);
            o.y = fmaf(acc[4 * k + 1], inv, bb.y);
            o.z = fmaf(acc[4 * k + 2], inv, bb.z);
            o.w = fmaf(acc[4 * k + 3], inv, bb.w);
            *(float4*)(op + 4 * k) = o;
        }
    }
}

extern "C" void kernel_launch(void* const* d_in, const int* in_sizes, int n_in,
                              void* d_out, int out_size) {
    const int*   x     = (const int*)d_in[0];     // [B,DAYS,N] = [16,10000]
    const int*   adj   = (const int*)d_in[1];     // [2,E]
    const float* emb   = (const float*)d_in[2];   // [N,32]
    const float* W     = (const float*)d_in[3];   // [32,128]
    const float* att_s = (const float*)d_in[4];   // [4,32]
    const float* att_d = (const float*)d_in[5];   // [4,32]
    const float* bias  = (const float*)d_in[6];   // [128]
    float* out = (float*)d_out;                   // [16,10000,128]

    k_all<<<GRID, TPB>>>(emb, W, att_s, att_d, x, adj, bias, out);
}